// round 3
// baseline (speedup 1.0000x reference)
#include <cuda_runtime.h>
#include <math.h>

// ---------------- problem constants ----------------
#define BB 64
#define TT 32
#define HH 512
#define MM 256
#define WWD 64
#define RR 4
#define IFACE 471
#define G4H 2048           // 4*H
#define NNOUT 768
#define CLIPV 20.0f
#define DELTA 1e-6f

// ---------------- device state ----------------
__device__ float g_xproj[BB*TT*G4H];        // x @ Wih0[:, :256]^T + bih0 + bhh0, layout [b][t][j]
__device__ float g_p0[2*BB*G4H];            // split-K partials for gates0
__device__ float g_p1[2*BB*G4H];            // split-K partials for gates1
__device__ float g_px[2*BB*480];            // split-K partials for xi (ldc=480)
__device__ float g_cat[BB*1024];            // [h0_ (512) | h1_ (512)] per batch
__device__ float g_c0[BB*HH];
__device__ float g_c1[BB*HH];
__device__ float g_outb[BB*HH];             // clipped h1 (controller output)
__device__ float g_mem[BB*MM*WWD];
__device__ float g_link[BB*MM*MM];          // 4.19M floats
__device__ float g_prec[BB*MM];
__device__ float g_rw[BB*RR*MM];
__device__ float g_ww[BB*MM];
__device__ float g_usage[BB*MM];
__device__ float g_ys[BB*TT*NNOUT];         // [b][t][ out(512) | rvec(256) ]
__device__ float g_W1[G4H*1024];            // [Wih1 | Whh1] concat along K

// ---------------- helpers ----------------
__device__ __forceinline__ float sigf(float x) { return 1.f / (1.f + expf(-x)); }
__device__ __forceinline__ float splusf(float x) {
    return (x > 0.f) ? (x + log1pf(expf(-x))) : log1pf(expf(x));
}

__device__ __forceinline__ float blk_max(float v, float* s, int tid) {
    s[tid] = v; __syncthreads();
    #pragma unroll
    for (int o = 128; o > 0; o >>= 1) {
        if (tid < o) s[tid] = fmaxf(s[tid], s[tid + o]);
        __syncthreads();
    }
    float r = s[0]; __syncthreads();
    return r;
}
__device__ __forceinline__ float blk_sum(float v, float* s, int tid) {
    s[tid] = v; __syncthreads();
    #pragma unroll
    for (int o = 128; o > 0; o >>= 1) {
        if (tid < o) s[tid] = s[tid] + s[tid + o];
        __syncthreads();
    }
    float r = s[0]; __syncthreads();
    return r;
}

// ---------------- generic C = A * B^T (B row-major [N][K]) ----------------
// TM=64 rows, TN=32 cols, 256 threads, thread tile 4x2. Optional split-K via grid.z
// writing partials at C + z*zstride. Optional per-column biases (only when no split).
#define TKC 16
__global__ void gemm_bt(const float* __restrict__ A, int lda,
                        const float* __restrict__ Bw, int ldb,
                        float* __restrict__ C, int ldc, long zstride,
                        int N, int Klen,
                        const float* __restrict__ bias0,
                        const float* __restrict__ bias1)
{
    __shared__ float As[TKC][68];   // k-major, padded for float4 + banks
    __shared__ float Bs[TKC][34];

    const int tid = threadIdx.x;
    const int tx = tid & 15;        // n
    const int ty = tid >> 4;        // m
    const int row0 = blockIdx.y * 64;
    const int n0 = blockIdx.x * 32;
    const int kstart = blockIdx.z * Klen;
    C += (long)blockIdx.z * zstride;

    float acc[4][2] = {};

    const int la_m = tid >> 2;           // 0..63
    const int la_k = (tid & 3) * 4;      // 0,4,8,12
    const int lb_n = tid >> 3;           // 0..31
    const int lb_k = (tid & 7) * 2;      // 0..14 step 2

    const float* Ab = A + (long)(row0 + la_m) * lda + kstart + la_k;
    const bool bvalid = (n0 + lb_n) < N;
    const float* Bb = Bw + (long)(n0 + lb_n) * ldb + kstart + lb_k;

    for (int k0 = 0; k0 < Klen; k0 += TKC) {
        float a0 = Ab[0], a1 = Ab[1], a2 = Ab[2], a3 = Ab[3];
        float b0 = 0.f, b1 = 0.f;
        if (bvalid) { b0 = Bb[0]; b1 = Bb[1]; }
        __syncthreads();
        As[la_k + 0][la_m] = a0; As[la_k + 1][la_m] = a1;
        As[la_k + 2][la_m] = a2; As[la_k + 3][la_m] = a3;
        Bs[lb_k][lb_n] = b0; Bs[lb_k + 1][lb_n] = b1;
        __syncthreads();
        #pragma unroll
        for (int kk = 0; kk < TKC; kk++) {
            float4 av = *(const float4*)&As[kk][ty * 4];
            float2 bv = *(const float2*)&Bs[kk][tx * 2];
            acc[0][0] += av.x * bv.x; acc[0][1] += av.x * bv.y;
            acc[1][0] += av.y * bv.x; acc[1][1] += av.y * bv.y;
            acc[2][0] += av.z * bv.x; acc[2][1] += av.z * bv.y;
            acc[3][0] += av.w * bv.x; acc[3][1] += av.w * bv.y;
        }
        Ab += TKC; Bb += TKC;
    }
    #pragma unroll
    for (int i = 0; i < 4; i++) {
        int m = row0 + ty * 4 + i;
        #pragma unroll
        for (int j = 0; j < 2; j++) {
            int n = n0 + tx * 2 + j;
            if (n < N) {
                float v = acc[i][j];
                if (bias0) v += bias0[n];
                if (bias1) v += bias1[n];
                C[(long)m * ldc + n] = v;
            }
        }
    }
}

// ---------------- init ----------------
__global__ void init_kernel(const float* __restrict__ h0in,
                            const float* __restrict__ Wih1,
                            const float* __restrict__ Whh1)
{
    int i = blockIdx.x * 256 + threadIdx.x;
    if (i < BB * MM * MM) g_link[i] = 0.f;
    if (i < BB * MM * WWD) g_mem[i] = DELTA;
    if (i < G4H * 1024) {
        int n = i >> 10, k = i & 1023;
        g_W1[i] = (k < 512) ? Wih1[n * 512 + k] : Whh1[n * 512 + (k - 512)];
    }
    if (i < BB * 1024) {
        int b = i >> 10, c = i & 1023;
        g_cat[i] = (c < 512) ? h0in[b * 512 + c] : h0in[32768 + b * 512 + (c - 512)];
    }
    if (i < BB * HH) { g_c0[i] = h0in[i]; g_c1[i] = h0in[32768 + i]; }
    if (i < BB * RR * MM) g_rw[i] = DELTA;
    if (i < BB * MM) { g_ww[i] = DELTA; g_usage[i] = 0.f; g_prec[i] = 0.f; }
}

// ---------------- LSTM cells ----------------
__global__ void cell0_kernel(int t)
{
    int idx = blockIdx.x * 256 + threadIdx.x;     // < 32768
    int b = idx >> 9, h = idx & 511;
    const float* xp = g_xproj + (long)(b * TT + t) * G4H;
    long base = (long)b * G4H;
    const long Z = (long)BB * G4H;
    float gi = xp[h]         + g_p0[base + h]         + g_p0[Z + base + h];
    float gf = xp[h + 512]   + g_p0[base + h + 512]   + g_p0[Z + base + h + 512];
    float gg = xp[h + 1024]  + g_p0[base + h + 1024]  + g_p0[Z + base + h + 1024];
    float go = xp[h + 1536]  + g_p0[base + h + 1536]  + g_p0[Z + base + h + 1536];
    float c = sigf(gf) * g_c0[idx] + sigf(gi) * tanhf(gg);
    g_c0[idx] = c;
    g_cat[b * 1024 + h] = sigf(go) * tanhf(c);
}

__global__ void cell1_kernel(int t, const float* __restrict__ bih1,
                             const float* __restrict__ bhh1)
{
    int idx = blockIdx.x * 256 + threadIdx.x;
    int b = idx >> 9, h = idx & 511;
    long base = (long)b * G4H;
    const long Z = (long)BB * G4H;
    float gi = bih1[h]        + bhh1[h]        + g_p1[base + h]        + g_p1[Z + base + h];
    float gf = bih1[h + 512]  + bhh1[h + 512]  + g_p1[base + h + 512]  + g_p1[Z + base + h + 512];
    float gg = bih1[h + 1024] + bhh1[h + 1024] + g_p1[base + h + 1024] + g_p1[Z + base + h + 1024];
    float go = bih1[h + 1536] + bhh1[h + 1536] + g_p1[base + h + 1536] + g_p1[Z + base + h + 1536];
    float c = sigf(gf) * g_c1[idx] + sigf(gi) * tanhf(gg);
    g_c1[idx] = c;
    float h1 = sigf(go) * tanhf(c);
    g_cat[b * 1024 + 512 + h] = h1;                 // carry raw h1
    float o = fminf(fmaxf(h1, -CLIPV), CLIPV);
    g_outb[b * 512 + h] = o;
    g_ys[(long)(b * TT + t) * NNOUT + h] = o;
}

// ---------------- memory step: one block per batch element ----------------
// dynamic smem layout (floats):
//   s_mem 256*65 | s_rwo 1024 | s_rwn 1024 | s_fwd 1024 | s_bwd 1024 | s_rcw 1024
//   s_ww 256 | s_wwo 256 | s_prec 256 | s_alloc 256 | s_wcw 256 | s_key 256
//   s_idx 256(int) | s_xi 480 | s_red 256 | s_rm 16
#define MEM_SMEM_FLOATS (256*65 + 5*1024 + 6*256 + 256 + 480 + 256 + 16)

__global__ void mem_kernel(int t, const float* __restrict__ bif)
{
    extern __shared__ float sm[];
    float* s_mem  = sm;
    float* s_rwo  = s_mem + 256 * 65;
    float* s_rwn  = s_rwo + 1024;
    float* s_fwd  = s_rwn + 1024;
    float* s_bwd  = s_fwd + 1024;
    float* s_rcw  = s_bwd + 1024;
    float* s_ww   = s_rcw + 1024;
    float* s_wwo  = s_ww + 256;
    float* s_prec = s_wwo + 256;
    float* s_alloc= s_prec + 256;
    float* s_wcw  = s_alloc + 256;
    float* s_key  = s_wcw + 256;
    int*   s_idx  = (int*)(s_key + 256);
    float* s_xi   = (float*)(s_idx + 256);
    float* s_red  = s_xi + 480;
    float* s_rm   = s_red + 256;

    const int tid = threadIdx.x;
    const int b = blockIdx.x;
    const int m = tid;

    // ---- load xi partials, apply activations ----
    const int PXZ = BB * 480;
    for (int i = tid; i < IFACE; i += 256) {
        float v = bif[i] + g_px[b * 480 + i] + g_px[PXZ + b * 480 + i];
        if      (i < 256) v = tanhf(v);
        else if (i < 260) v = splusf(v);
        else if (i < 324) v = tanhf(v);
        else if (i == 324) v = splusf(v);
        else if (i < 389) v = sigf(v);
        else if (i < 453) v = tanhf(v);
        else if (i < 459) v = sigf(v);
        // 459..470: raw (softmax below)
        s_xi[i] = v;
    }
    for (int i = tid; i < 1024; i += 256) s_rwo[i] = g_rw[b * 1024 + i];
    s_wwo[tid]  = g_ww[b * 256 + tid];
    s_prec[tid] = g_prec[b * 256 + tid];
    for (int i = tid; i < MM * WWD; i += 256)
        s_mem[(i >> 6) * 65 + (i & 63)] = g_mem[(long)b * MM * WWD + i];
    __syncthreads();

    // read-mode softmax (4 triples)
    if (tid < 4) {
        float a = s_xi[459 + tid * 3], bb2 = s_xi[460 + tid * 3], cc = s_xi[461 + tid * 3];
        float mx = fmaxf(a, fmaxf(bb2, cc));
        float ea = expf(a - mx), eb = expf(bb2 - mx), ec = expf(cc - mx);
        float s = ea + eb + ec;
        s_rm[tid * 3] = ea / s; s_rm[tid * 3 + 1] = eb / s; s_rm[tid * 3 + 2] = ec / s;
    }
    __syncthreads();

    // ---- usage update (old ww, old rw) ----
    float u = g_usage[b * 256 + m];
    u = u + (1.f - u) * s_wwo[m];
    float psi = 1.f;
    #pragma unroll
    for (int r = 0; r < 4; r++) psi *= 1.f - s_xi[453 + r] * s_rwo[r * 256 + m];
    u *= psi;
    g_usage[b * 256 + m] = u;

    // ---- write content weights on OLD memory ----
    float nk = 0.f;
    #pragma unroll 8
    for (int w = 0; w < 64; w++) { float kv = s_xi[260 + w]; nk += kv * kv; }
    nk = sqrtf(nk) + DELTA;
    float nm = 0.f, dot = 0.f;
    #pragma unroll 8
    for (int w = 0; w < 64; w++) {
        float mv = s_mem[m * 65 + w];
        nm += mv * mv; dot += mv * s_xi[260 + w];
    }
    nm = sqrtf(nm) + DELTA;
    float z = (dot / (nm * nk)) * s_xi[324];
    float mx = blk_max(z, s_red, tid);
    float e = expf(z - mx);
    float ssum = blk_sum(e, s_red, tid);
    s_wcw[m] = e / ssum;

    // ---- allocation: stable ascending sort of u' = DELTA+(1-DELTA)*u ----
    s_key[m] = DELTA + (1.f - DELTA) * u;
    s_idx[m] = m;
    __syncthreads();
    for (int k = 2; k <= 256; k <<= 1) {
        for (int j = k >> 1; j > 0; j >>= 1) {
            int i = tid, l = i ^ j;
            if (l > i) {
                bool up = ((i & k) == 0);
                float ki = s_key[i], kl = s_key[l];
                int ii = s_idx[i], il = s_idx[l];
                bool igt = (ki > kl) || (ki == kl && ii > il);
                if (igt == up) { s_key[i] = kl; s_key[l] = ki; s_idx[i] = il; s_idx[l] = ii; }
            }
            __syncthreads();
        }
    }
    // exclusive cumprod via inclusive product scan
    s_red[tid] = s_key[tid]; __syncthreads();
    for (int off = 1; off < 256; off <<= 1) {
        float prev = (tid >= off) ? s_red[tid - off] : 1.f;
        __syncthreads();
        s_red[tid] *= prev;
        __syncthreads();
    }
    float excl = (tid == 0) ? 1.f : s_red[tid - 1];
    float sa = (1.f - s_key[tid]) * excl;
    s_alloc[s_idx[tid]] = sa;
    __syncthreads();

    // ---- new write weights ----
    float ag = s_xi[457], wg = s_xi[458];
    float wwn = wg * (ag * s_alloc[m] + (1.f - ag) * s_wcw[m]);
    s_ww[m] = wwn;
    float sumww = blk_sum(wwn, s_red, tid);

    // ---- memory erase + write (in smem) ----
    #pragma unroll 8
    for (int w = 0; w < 64; w++) {
        float mv = s_mem[m * 65 + w];
        s_mem[m * 65 + w] = mv * (1.f - wwn * s_xi[325 + w]) + wwn * s_xi[389 + w];
    }
    __syncthreads();
    for (int i = tid; i < MM * WWD; i += 256)
        g_mem[(long)b * MM * WWD + i] = s_mem[(i >> 6) * 65 + (i & 63)];

    // ---- link update + fwd + bwd fused pass ----
    for (int i = tid; i < 1024; i += 256) { s_fwd[i] = 0.f; s_bwd[i] = 0.f; }
    __syncthreads();

    const int warp = tid >> 5, lane = tid & 31;
    float bw[4][8];
    #pragma unroll
    for (int r = 0; r < 4; r++)
        #pragma unroll
        for (int js = 0; js < 8; js++) bw[r][js] = 0.f;

    float* lrow = g_link + (long)b * MM * MM;
    for (int ii = 0; ii < 32; ii++) {
        int i = warp * 32 + ii;
        float wwi = s_ww[i];
        float rwi0 = s_rwo[i], rwi1 = s_rwo[256 + i], rwi2 = s_rwo[512 + i], rwi3 = s_rwo[768 + i];
        float f0 = 0.f, f1 = 0.f, f2 = 0.f, f3 = 0.f;
        #pragma unroll
        for (int js = 0; js < 8; js++) {
            int j = js * 32 + lane;
            float lo = lrow[i * 256 + j];
            float ln = (1.f - wwi - s_ww[j]) * lo + wwi * s_prec[j];
            if (j == i) ln = 0.f;
            lrow[i * 256 + j] = ln;
            f0 += ln * s_rwo[j];       f1 += ln * s_rwo[256 + j];
            f2 += ln * s_rwo[512 + j]; f3 += ln * s_rwo[768 + j];
            bw[0][js] += rwi0 * ln; bw[1][js] += rwi1 * ln;
            bw[2][js] += rwi2 * ln; bw[3][js] += rwi3 * ln;
        }
        #pragma unroll
        for (int o = 16; o > 0; o >>= 1) {
            f0 += __shfl_xor_sync(0xffffffffu, f0, o);
            f1 += __shfl_xor_sync(0xffffffffu, f1, o);
            f2 += __shfl_xor_sync(0xffffffffu, f2, o);
            f3 += __shfl_xor_sync(0xffffffffu, f3, o);
        }
        if (lane == 0) {
            s_fwd[i] = f0; s_fwd[256 + i] = f1; s_fwd[512 + i] = f2; s_fwd[768 + i] = f3;
        }
    }
    #pragma unroll
    for (int r = 0; r < 4; r++)
        #pragma unroll
        for (int js = 0; js < 8; js++)
            atomicAdd(&s_bwd[r * 256 + js * 32 + lane], bw[r][js]);
    __syncthreads();

    // ---- precedence update ----
    g_prec[b * 256 + tid] = (1.f - sumww) * s_prec[tid] + s_ww[tid];
    g_ww[b * 256 + tid] = s_ww[tid];

    // ---- read content weights on NEW memory ----
    float nk2[4];
    #pragma unroll
    for (int r = 0; r < 4; r++) {
        float acc = 0.f;
        #pragma unroll 8
        for (int w = 0; w < 64; w++) { float kv = s_xi[r * 64 + w]; acc += kv * kv; }
        nk2[r] = sqrtf(acc) + DELTA;
    }
    float nmn = 0.f, dots[4] = {0.f, 0.f, 0.f, 0.f};
    #pragma unroll 8
    for (int w = 0; w < 64; w++) {
        float mv = s_mem[m * 65 + w];
        nmn += mv * mv;
        dots[0] += mv * s_xi[0 * 64 + w];
        dots[1] += mv * s_xi[1 * 64 + w];
        dots[2] += mv * s_xi[2 * 64 + w];
        dots[3] += mv * s_xi[3 * 64 + w];
    }
    nmn = sqrtf(nmn) + DELTA;
    #pragma unroll
    for (int r = 0; r < 4; r++) {
        float zz = (dots[r] / (nmn * nk2[r])) * s_xi[256 + r];
        float mxr = blk_max(zz, s_red, tid);
        float er = expf(zz - mxr);
        float sr = blk_sum(er, s_red, tid);
        s_rcw[r * 256 + m] = er / sr;
    }
    __syncthreads();

    // ---- new read weights ----
    #pragma unroll
    for (int r = 0; r < 4; r++) {
        float rn = s_rm[r * 3] * s_bwd[r * 256 + m]
                 + s_rm[r * 3 + 1] * s_fwd[r * 256 + m]
                 + s_rm[r * 3 + 2] * s_rcw[r * 256 + m];
        s_rwn[r * 256 + m] = rn;
        g_rw[b * 1024 + r * 256 + m] = rn;
    }
    __syncthreads();

    // ---- read vectors ----
    int r = tid >> 6, w = tid & 63;
    float acc = 0.f;
    for (int mm = 0; mm < 256; mm++) acc += s_rwn[r * 256 + mm] * s_mem[mm * 65 + w];
    g_ys[(long)(b * TT + t) * NNOUT + 512 + tid] = acc;
}

// ---------------- elementwise tanh on ys ----------------
__global__ void tanh_kernel()
{
    int i = blockIdx.x * 256 + threadIdx.x;
    if (i < BB * TT * NNOUT) g_ys[i] = tanhf(g_ys[i]);
}

// ---------------- host orchestration ----------------
extern "C" void kernel_launch(void* const* d_in, const int* in_sizes, int n_in,
                              void* d_out, int out_size)
{
    const float* x    = (const float*)d_in[0];
    const float* h0   = (const float*)d_in[1];
    const float* Wih0 = (const float*)d_in[2];
    const float* Whh0 = (const float*)d_in[3];
    const float* bih0 = (const float*)d_in[4];
    const float* bhh0 = (const float*)d_in[5];
    const float* Wih1 = (const float*)d_in[6];
    const float* Whh1 = (const float*)d_in[7];
    const float* bih1 = (const float*)d_in[8];
    const float* bhh1 = (const float*)d_in[9];
    const float* Wif  = (const float*)d_in[10];
    const float* bif  = (const float*)d_in[11];
    const float* Wout = (const float*)d_in[12];
    const float* bout = (const float*)d_in[13];
    float* out = (float*)d_out;
    (void)in_sizes; (void)n_in; (void)out_size;

    cudaFuncSetAttribute(mem_kernel, cudaFuncAttributeMaxDynamicSharedMemorySize,
                         MEM_SMEM_FLOATS * 4);

    float *p_xproj, *p_p0, *p_p1, *p_px, *p_cat, *p_outb, *p_ys, *p_W1;
    cudaGetSymbolAddress((void**)&p_xproj, g_xproj);
    cudaGetSymbolAddress((void**)&p_p0, g_p0);
    cudaGetSymbolAddress((void**)&p_p1, g_p1);
    cudaGetSymbolAddress((void**)&p_px, g_px);
    cudaGetSymbolAddress((void**)&p_cat, g_cat);
    cudaGetSymbolAddress((void**)&p_outb, g_outb);
    cudaGetSymbolAddress((void**)&p_ys, g_ys);
    cudaGetSymbolAddress((void**)&p_W1, g_W1);

    // init state + build fused W1
    init_kernel<<<16384, 256>>>(h0, Wih1, Whh1);

    // xproj: (B*T,256) @ Wih0[:, :256]^T + (bih0+bhh0)   -> [b][t][4H]
    gemm_bt<<<dim3(G4H / 32, (BB * TT) / 64, 1), 256>>>(
        x, 256, Wih0, 512, p_xproj, G4H, 0L, G4H, 256, bih0, bhh0);

    const long Z0 = (long)BB * G4H;
    const long ZX = (long)BB * 480;

    for (int t = 0; t < TT; t++) {
        // gates0 partials: h0 @ Whh0^T   (K=512 split 2)
        gemm_bt<<<dim3(G4H / 32, 1, 2), 256>>>(
            p_cat, 1024, Whh0, 512, p_p0, G4H, Z0, G4H, 256, nullptr, nullptr);
        cell0_kernel<<<128, 256>>>(t);

        // gates1 partials: [h0_new|h1_old] @ [Wih1;Whh1]^T  (K=1024 split 2)
        gemm_bt<<<dim3(G4H / 32, 1, 2), 256>>>(
            p_cat, 1024, p_W1, 1024, p_p1, G4H, Z0, G4H, 512, nullptr, nullptr);
        cell1_kernel<<<128, 256>>>(t, bih1, bhh1);

        // xi partials: out @ Wif^T  (N=471, K=512 split 2)
        gemm_bt<<<dim3(15, 1, 2), 256>>>(
            p_outb, 512, Wif, 512, p_px, 480, ZX, IFACE, 256, nullptr, nullptr);

        mem_kernel<<<BB, 256, MEM_SMEM_FLOATS * 4>>>(t, bif);
    }

    // final: out[b][t][o] = tanh(ys) @ Wout^T + bout
    tanh_kernel<<<(BB * TT * NNOUT + 255) / 256, 256>>>();
    gemm_bt<<<dim3(256 / 32, (BB * TT) / 64, 1), 256>>>(
        p_ys, NNOUT, Wout, NNOUT, out, 256, 0L, 256, NNOUT, bout, nullptr);
}

// round 4
// speedup vs baseline: 1.0032x; 1.0032x over previous
#include <cuda_runtime.h>
#include <math.h>

// ---------------- problem constants ----------------
#define BB 64
#define TT 32
#define HH 512
#define MM 256
#define WWD 64
#define RR 4
#define IFACE 471
#define G4H 2048           // 4*H
#define NNOUT 768
#define CLIPV 20.0f
#define DELTA 1e-6f

// ---------------- device state ----------------
__device__ float g_xproj[BB*TT*G4H];        // x @ Wih0[:, :256]^T + bih0 + bhh0, layout [b][t][j]
__device__ float g_p0[2*BB*G4H];            // split-K partials for gates0
__device__ float g_p1[2*BB*G4H];            // split-K partials for gates1
__device__ float g_px[2*BB*480];            // split-K partials for xi (ldc=480)
__device__ float g_cat[BB*1024];            // [h0_ (512) | h1_ (512)] per batch
__device__ float g_c0[BB*HH];
__device__ float g_c1[BB*HH];
__device__ float g_outb[BB*HH];             // clipped h1 (controller output)
__device__ float g_mem[BB*MM*WWD];
__device__ float g_link[BB*MM*MM];          // 4.19M floats
__device__ float g_prec[BB*MM];
__device__ float g_rw[BB*RR*MM];
__device__ float g_ww[BB*MM];
__device__ float g_usage[BB*MM];
__device__ float g_ys[BB*TT*NNOUT];         // [b][t][ out(512) | rvec(256) ]
__device__ float g_W1[G4H*1024];            // [Wih1 | Whh1] concat along K

// ---------------- helpers ----------------
__device__ __forceinline__ float sigf(float x) { return 1.f / (1.f + expf(-x)); }
__device__ __forceinline__ float splusf(float x) {
    return (x > 0.f) ? (x + log1pf(expf(-x))) : log1pf(expf(x));
}

__device__ __forceinline__ float blk_max(float v, float* s, int tid) {
    s[tid] = v; __syncthreads();
    #pragma unroll
    for (int o = 128; o > 0; o >>= 1) {
        if (tid < o) s[tid] = fmaxf(s[tid], s[tid + o]);
        __syncthreads();
    }
    float r = s[0]; __syncthreads();
    return r;
}
__device__ __forceinline__ float blk_sum(float v, float* s, int tid) {
    s[tid] = v; __syncthreads();
    #pragma unroll
    for (int o = 128; o > 0; o >>= 1) {
        if (tid < o) s[tid] = s[tid] + s[tid + o];
        __syncthreads();
    }
    float r = s[0]; __syncthreads();
    return r;
}

// ---------------- generic C = A * B^T (B row-major [N][K]) ----------------
// TM=64 rows, TN=32 cols, 256 threads, thread tile 4x2. Optional split-K via grid.z
// writing partials at C + z*zstride. Optional per-column biases (only when no split).
#define TKC 16
__global__ void gemm_bt(const float* __restrict__ A, int lda,
                        const float* __restrict__ Bw, int ldb,
                        float* __restrict__ C, int ldc, long zstride,
                        int N, int Klen,
                        const float* __restrict__ bias0,
                        const float* __restrict__ bias1)
{
    __shared__ float As[TKC][68];   // k-major, padded for float4 + banks
    __shared__ float Bs[TKC][34];

    const int tid = threadIdx.x;
    const int tx = tid & 15;        // n
    const int ty = tid >> 4;        // m
    const int row0 = blockIdx.y * 64;
    const int n0 = blockIdx.x * 32;
    const int kstart = blockIdx.z * Klen;
    C += (long)blockIdx.z * zstride;

    float acc[4][2] = {};

    const int la_m = tid >> 2;           // 0..63
    const int la_k = (tid & 3) * 4;      // 0,4,8,12
    const int lb_n = tid >> 3;           // 0..31
    const int lb_k = (tid & 7) * 2;      // 0..14 step 2

    const float* Ab = A + (long)(row0 + la_m) * lda + kstart + la_k;
    const bool bvalid = (n0 + lb_n) < N;
    const float* Bb = Bw + (long)(n0 + lb_n) * ldb + kstart + lb_k;

    for (int k0 = 0; k0 < Klen; k0 += TKC) {
        float a0 = Ab[0], a1 = Ab[1], a2 = Ab[2], a3 = Ab[3];
        float b0 = 0.f, b1 = 0.f;
        if (bvalid) { b0 = Bb[0]; b1 = Bb[1]; }
        __syncthreads();
        As[la_k + 0][la_m] = a0; As[la_k + 1][la_m] = a1;
        As[la_k + 2][la_m] = a2; As[la_k + 3][la_m] = a3;
        Bs[lb_k][lb_n] = b0; Bs[lb_k + 1][lb_n] = b1;
        __syncthreads();
        #pragma unroll
        for (int kk = 0; kk < TKC; kk++) {
            float4 av = *(const float4*)&As[kk][ty * 4];
            float2 bv = *(const float2*)&Bs[kk][tx * 2];
            acc[0][0] += av.x * bv.x; acc[0][1] += av.x * bv.y;
            acc[1][0] += av.y * bv.x; acc[1][1] += av.y * bv.y;
            acc[2][0] += av.z * bv.x; acc[2][1] += av.z * bv.y;
            acc[3][0] += av.w * bv.x; acc[3][1] += av.w * bv.y;
        }
        Ab += TKC; Bb += TKC;
    }
    #pragma unroll
    for (int i = 0; i < 4; i++) {
        int m = row0 + ty * 4 + i;
        #pragma unroll
        for (int j = 0; j < 2; j++) {
            int n = n0 + tx * 2 + j;
            if (n < N) {
                float v = acc[i][j];
                if (bias0) v += bias0[n];
                if (bias1) v += bias1[n];
                C[(long)m * ldc + n] = v;
            }
        }
    }
}

// ---------------- init ----------------
__global__ void init_kernel(const float* __restrict__ h0in,
                            const float* __restrict__ Wih1,
                            const float* __restrict__ Whh1)
{
    int i = blockIdx.x * 256 + threadIdx.x;
    if (i < BB * MM * MM) g_link[i] = 0.f;
    if (i < BB * MM * WWD) g_mem[i] = DELTA;
    if (i < G4H * 1024) {
        int n = i >> 10, k = i & 1023;
        g_W1[i] = (k < 512) ? Wih1[n * 512 + k] : Whh1[n * 512 + (k - 512)];
    }
    if (i < BB * 1024) {
        int b = i >> 10, c = i & 1023;
        g_cat[i] = (c < 512) ? h0in[b * 512 + c] : h0in[32768 + b * 512 + (c - 512)];
    }
    if (i < BB * HH) { g_c0[i] = h0in[i]; g_c1[i] = h0in[32768 + i]; }
    if (i < BB * RR * MM) g_rw[i] = DELTA;
    if (i < BB * MM) { g_ww[i] = DELTA; g_usage[i] = 0.f; g_prec[i] = 0.f; }
}

// ---------------- LSTM cells ----------------
__global__ void cell0_kernel(int t)
{
    int idx = blockIdx.x * 256 + threadIdx.x;     // < 32768
    int b = idx >> 9, h = idx & 511;
    const float* xp = g_xproj + (long)(b * TT + t) * G4H;
    long base = (long)b * G4H;
    const long Z = (long)BB * G4H;
    float gi = xp[h]         + g_p0[base + h]         + g_p0[Z + base + h];
    float gf = xp[h + 512]   + g_p0[base + h + 512]   + g_p0[Z + base + h + 512];
    float gg = xp[h + 1024]  + g_p0[base + h + 1024]  + g_p0[Z + base + h + 1024];
    float go = xp[h + 1536]  + g_p0[base + h + 1536]  + g_p0[Z + base + h + 1536];
    float c = sigf(gf) * g_c0[idx] + sigf(gi) * tanhf(gg);
    g_c0[idx] = c;
    g_cat[b * 1024 + h] = sigf(go) * tanhf(c);
}

__global__ void cell1_kernel(int t, const float* __restrict__ bih1,
                             const float* __restrict__ bhh1)
{
    int idx = blockIdx.x * 256 + threadIdx.x;
    int b = idx >> 9, h = idx & 511;
    long base = (long)b * G4H;
    const long Z = (long)BB * G4H;
    float gi = bih1[h]        + bhh1[h]        + g_p1[base + h]        + g_p1[Z + base + h];
    float gf = bih1[h + 512]  + bhh1[h + 512]  + g_p1[base + h + 512]  + g_p1[Z + base + h + 512];
    float gg = bih1[h + 1024] + bhh1[h + 1024] + g_p1[base + h + 1024] + g_p1[Z + base + h + 1024];
    float go = bih1[h + 1536] + bhh1[h + 1536] + g_p1[base + h + 1536] + g_p1[Z + base + h + 1536];
    float c = sigf(gf) * g_c1[idx] + sigf(gi) * tanhf(gg);
    g_c1[idx] = c;
    float h1 = sigf(go) * tanhf(c);
    g_cat[b * 1024 + 512 + h] = h1;                 // carry raw h1
    float o = fminf(fmaxf(h1, -CLIPV), CLIPV);
    g_outb[b * 512 + h] = o;
    g_ys[(long)(b * TT + t) * NNOUT + h] = o;
}

// ---------------- memory step: one block per batch element ----------------
// dynamic smem layout (floats):
//   s_mem 256*65 | s_rwo 1024 | s_rwn 1024 | s_fwd 1024 | s_bwd 1024 | s_rcw 1024
//   s_ww 256 | s_wwo 256 | s_prec 256 | s_alloc 256 | s_wcw 256 | s_key 256
//   s_idx 256(int) | s_xi 480 | s_red 256 | s_rm 16
#define MEM_SMEM_FLOATS (256*65 + 5*1024 + 6*256 + 256 + 480 + 256 + 16)

__global__ void mem_kernel(int t, const float* __restrict__ bif)
{
    extern __shared__ float sm[];
    float* s_mem  = sm;
    float* s_rwo  = s_mem + 256 * 65;
    float* s_rwn  = s_rwo + 1024;
    float* s_fwd  = s_rwn + 1024;
    float* s_bwd  = s_fwd + 1024;
    float* s_rcw  = s_bwd + 1024;
    float* s_ww   = s_rcw + 1024;
    float* s_wwo  = s_ww + 256;
    float* s_prec = s_wwo + 256;
    float* s_alloc= s_prec + 256;
    float* s_wcw  = s_alloc + 256;
    float* s_key  = s_wcw + 256;
    int*   s_idx  = (int*)(s_key + 256);
    float* s_xi   = (float*)(s_idx + 256);
    float* s_red  = s_xi + 480;
    float* s_rm   = s_red + 256;

    const int tid = threadIdx.x;
    const int b = blockIdx.x;
    const int m = tid;

    // ---- load xi partials, apply activations ----
    const int PXZ = BB * 480;
    for (int i = tid; i < IFACE; i += 256) {
        float v = bif[i] + g_px[b * 480 + i] + g_px[PXZ + b * 480 + i];
        if      (i < 256) v = tanhf(v);
        else if (i < 260) v = splusf(v);
        else if (i < 324) v = tanhf(v);
        else if (i == 324) v = splusf(v);
        else if (i < 389) v = sigf(v);
        else if (i < 453) v = tanhf(v);
        else if (i < 459) v = sigf(v);
        // 459..470: raw (softmax below)
        s_xi[i] = v;
    }
    for (int i = tid; i < 1024; i += 256) s_rwo[i] = g_rw[b * 1024 + i];
    s_wwo[tid]  = g_ww[b * 256 + tid];
    s_prec[tid] = g_prec[b * 256 + tid];
    for (int i = tid; i < MM * WWD; i += 256)
        s_mem[(i >> 6) * 65 + (i & 63)] = g_mem[(long)b * MM * WWD + i];
    __syncthreads();

    // read-mode softmax (4 triples)
    if (tid < 4) {
        float a = s_xi[459 + tid * 3], bb2 = s_xi[460 + tid * 3], cc = s_xi[461 + tid * 3];
        float mx = fmaxf(a, fmaxf(bb2, cc));
        float ea = expf(a - mx), eb = expf(bb2 - mx), ec = expf(cc - mx);
        float s = ea + eb + ec;
        s_rm[tid * 3] = ea / s; s_rm[tid * 3 + 1] = eb / s; s_rm[tid * 3 + 2] = ec / s;
    }
    __syncthreads();

    // ---- usage update (old ww, old rw) ----
    float u = g_usage[b * 256 + m];
    u = u + (1.f - u) * s_wwo[m];
    float psi = 1.f;
    #pragma unroll
    for (int r = 0; r < 4; r++) psi *= 1.f - s_xi[453 + r] * s_rwo[r * 256 + m];
    u *= psi;
    g_usage[b * 256 + m] = u;

    // ---- write content weights on OLD memory ----
    float nk = 0.f;
    #pragma unroll 8
    for (int w = 0; w < 64; w++) { float kv = s_xi[260 + w]; nk += kv * kv; }
    nk = sqrtf(nk) + DELTA;
    float nm = 0.f, dot = 0.f;
    #pragma unroll 8
    for (int w = 0; w < 64; w++) {
        float mv = s_mem[m * 65 + w];
        nm += mv * mv; dot += mv * s_xi[260 + w];
    }
    nm = sqrtf(nm) + DELTA;
    float z = (dot / (nm * nk)) * s_xi[324];
    float mx = blk_max(z, s_red, tid);
    float e = expf(z - mx);
    float ssum = blk_sum(e, s_red, tid);
    s_wcw[m] = e / ssum;

    // ---- allocation: stable ascending sort of u' = DELTA+(1-DELTA)*u ----
    s_key[m] = DELTA + (1.f - DELTA) * u;
    s_idx[m] = m;
    __syncthreads();
    for (int k = 2; k <= 256; k <<= 1) {
        for (int j = k >> 1; j > 0; j >>= 1) {
            int i = tid, l = i ^ j;
            if (l > i) {
                bool up = ((i & k) == 0);
                float ki = s_key[i], kl = s_key[l];
                int ii = s_idx[i], il = s_idx[l];
                bool igt = (ki > kl) || (ki == kl && ii > il);
                if (igt == up) { s_key[i] = kl; s_key[l] = ki; s_idx[i] = il; s_idx[l] = ii; }
            }
            __syncthreads();
        }
    }
    // exclusive cumprod via inclusive product scan
    s_red[tid] = s_key[tid]; __syncthreads();
    for (int off = 1; off < 256; off <<= 1) {
        float prev = (tid >= off) ? s_red[tid - off] : 1.f;
        __syncthreads();
        s_red[tid] *= prev;
        __syncthreads();
    }
    float excl = (tid == 0) ? 1.f : s_red[tid - 1];
    float sa = (1.f - s_key[tid]) * excl;
    s_alloc[s_idx[tid]] = sa;
    __syncthreads();

    // ---- new write weights ----
    float ag = s_xi[457], wg = s_xi[458];
    float wwn = wg * (ag * s_alloc[m] + (1.f - ag) * s_wcw[m]);
    s_ww[m] = wwn;
    float sumww = blk_sum(wwn, s_red, tid);

    // ---- memory erase + write (in smem) ----
    #pragma unroll 8
    for (int w = 0; w < 64; w++) {
        float mv = s_mem[m * 65 + w];
        s_mem[m * 65 + w] = mv * (1.f - wwn * s_xi[325 + w]) + wwn * s_xi[389 + w];
    }
    __syncthreads();
    for (int i = tid; i < MM * WWD; i += 256)
        g_mem[(long)b * MM * WWD + i] = s_mem[(i >> 6) * 65 + (i & 63)];

    // ---- link update + fwd + bwd fused pass ----
    for (int i = tid; i < 1024; i += 256) { s_fwd[i] = 0.f; s_bwd[i] = 0.f; }
    __syncthreads();

    const int warp = tid >> 5, lane = tid & 31;
    float bw[4][8];
    #pragma unroll
    for (int r = 0; r < 4; r++)
        #pragma unroll
        for (int js = 0; js < 8; js++) bw[r][js] = 0.f;

    float* lrow = g_link + (long)b * MM * MM;
    for (int ii = 0; ii < 32; ii++) {
        int i = warp * 32 + ii;
        float wwi = s_ww[i];
        float rwi0 = s_rwo[i], rwi1 = s_rwo[256 + i], rwi2 = s_rwo[512 + i], rwi3 = s_rwo[768 + i];
        float f0 = 0.f, f1 = 0.f, f2 = 0.f, f3 = 0.f;
        #pragma unroll
        for (int js = 0; js < 8; js++) {
            int j = js * 32 + lane;
            float lo = lrow[i * 256 + j];
            float ln = (1.f - wwi - s_ww[j]) * lo + wwi * s_prec[j];
            if (j == i) ln = 0.f;
            lrow[i * 256 + j] = ln;
            f0 += ln * s_rwo[j];       f1 += ln * s_rwo[256 + j];
            f2 += ln * s_rwo[512 + j]; f3 += ln * s_rwo[768 + j];
            bw[0][js] += rwi0 * ln; bw[1][js] += rwi1 * ln;
            bw[2][js] += rwi2 * ln; bw[3][js] += rwi3 * ln;
        }
        #pragma unroll
        for (int o = 16; o > 0; o >>= 1) {
            f0 += __shfl_xor_sync(0xffffffffu, f0, o);
            f1 += __shfl_xor_sync(0xffffffffu, f1, o);
            f2 += __shfl_xor_sync(0xffffffffu, f2, o);
            f3 += __shfl_xor_sync(0xffffffffu, f3, o);
        }
        if (lane == 0) {
            s_fwd[i] = f0; s_fwd[256 + i] = f1; s_fwd[512 + i] = f2; s_fwd[768 + i] = f3;
        }
    }
    #pragma unroll
    for (int r = 0; r < 4; r++)
        #pragma unroll
        for (int js = 0; js < 8; js++)
            atomicAdd(&s_bwd[r * 256 + js * 32 + lane], bw[r][js]);
    __syncthreads();

    // ---- precedence update ----
    g_prec[b * 256 + tid] = (1.f - sumww) * s_prec[tid] + s_ww[tid];
    g_ww[b * 256 + tid] = s_ww[tid];

    // ---- read content weights on NEW memory ----
    float nk2[4];
    #pragma unroll
    for (int r = 0; r < 4; r++) {
        float acc = 0.f;
        #pragma unroll 8
        for (int w = 0; w < 64; w++) { float kv = s_xi[r * 64 + w]; acc += kv * kv; }
        nk2[r] = sqrtf(acc) + DELTA;
    }
    float nmn = 0.f, dots[4] = {0.f, 0.f, 0.f, 0.f};
    #pragma unroll 8
    for (int w = 0; w < 64; w++) {
        float mv = s_mem[m * 65 + w];
        nmn += mv * mv;
        dots[0] += mv * s_xi[0 * 64 + w];
        dots[1] += mv * s_xi[1 * 64 + w];
        dots[2] += mv * s_xi[2 * 64 + w];
        dots[3] += mv * s_xi[3 * 64 + w];
    }
    nmn = sqrtf(nmn) + DELTA;
    #pragma unroll
    for (int r = 0; r < 4; r++) {
        float zz = (dots[r] / (nmn * nk2[r])) * s_xi[256 + r];
        float mxr = blk_max(zz, s_red, tid);
        float er = expf(zz - mxr);
        float sr = blk_sum(er, s_red, tid);
        s_rcw[r * 256 + m] = er / sr;
    }
    __syncthreads();

    // ---- new read weights ----
    #pragma unroll
    for (int r = 0; r < 4; r++) {
        float rn = s_rm[r * 3] * s_bwd[r * 256 + m]
                 + s_rm[r * 3 + 1] * s_fwd[r * 256 + m]
                 + s_rm[r * 3 + 2] * s_rcw[r * 256 + m];
        s_rwn[r * 256 + m] = rn;
        g_rw[b * 1024 + r * 256 + m] = rn;
    }
    __syncthreads();

    // ---- read vectors ----
    int r = tid >> 6, w = tid & 63;
    float acc = 0.f;
    for (int mm = 0; mm < 256; mm++) acc += s_rwn[r * 256 + mm] * s_mem[mm * 65 + w];
    g_ys[(long)(b * TT + t) * NNOUT + 512 + tid] = acc;
}

// ---------------- elementwise tanh on ys ----------------
__global__ void tanh_kernel()
{
    int i = blockIdx.x * 256 + threadIdx.x;
    if (i < BB * TT * NNOUT) g_ys[i] = tanhf(g_ys[i]);
}

// ---------------- host orchestration ----------------
extern "C" void kernel_launch(void* const* d_in, const int* in_sizes, int n_in,
                              void* d_out, int out_size)
{
    const float* x    = (const float*)d_in[0];
    const float* h0   = (const float*)d_in[1];
    const float* Wih0 = (const float*)d_in[2];
    const float* Whh0 = (const float*)d_in[3];
    const float* bih0 = (const float*)d_in[4];
    const float* bhh0 = (const float*)d_in[5];
    const float* Wih1 = (const float*)d_in[6];
    const float* Whh1 = (const float*)d_in[7];
    const float* bih1 = (const float*)d_in[8];
    const float* bhh1 = (const float*)d_in[9];
    const float* Wif  = (const float*)d_in[10];
    const float* bif  = (const float*)d_in[11];
    const float* Wout = (const float*)d_in[12];
    const float* bout = (const float*)d_in[13];
    float* out = (float*)d_out;
    (void)in_sizes; (void)n_in; (void)out_size;

    cudaFuncSetAttribute(mem_kernel, cudaFuncAttributeMaxDynamicSharedMemorySize,
                         MEM_SMEM_FLOATS * 4);

    float *p_xproj, *p_p0, *p_p1, *p_px, *p_cat, *p_outb, *p_ys, *p_W1;
    cudaGetSymbolAddress((void**)&p_xproj, g_xproj);
    cudaGetSymbolAddress((void**)&p_p0, g_p0);
    cudaGetSymbolAddress((void**)&p_p1, g_p1);
    cudaGetSymbolAddress((void**)&p_px, g_px);
    cudaGetSymbolAddress((void**)&p_cat, g_cat);
    cudaGetSymbolAddress((void**)&p_outb, g_outb);
    cudaGetSymbolAddress((void**)&p_ys, g_ys);
    cudaGetSymbolAddress((void**)&p_W1, g_W1);

    // init state + build fused W1
    init_kernel<<<16384, 256>>>(h0, Wih1, Whh1);

    // xproj: (B*T,256) @ Wih0[:, :256]^T + (bih0+bhh0)   -> [b][t][4H]
    gemm_bt<<<dim3(G4H / 32, (BB * TT) / 64, 1), 256>>>(
        x, 256, Wih0, 512, p_xproj, G4H, 0L, G4H, 256, bih0, bhh0);

    const long Z0 = (long)BB * G4H;
    const long ZX = (long)BB * 480;

    for (int t = 0; t < TT; t++) {
        // gates0 partials: h0 @ Whh0^T   (K=512 split 2)
        gemm_bt<<<dim3(G4H / 32, 1, 2), 256>>>(
            p_cat, 1024, Whh0, 512, p_p0, G4H, Z0, G4H, 256, nullptr, nullptr);
        cell0_kernel<<<128, 256>>>(t);

        // gates1 partials: [h0_new|h1_old] @ [Wih1;Whh1]^T  (K=1024 split 2)
        gemm_bt<<<dim3(G4H / 32, 1, 2), 256>>>(
            p_cat, 1024, p_W1, 1024, p_p1, G4H, Z0, G4H, 512, nullptr, nullptr);
        cell1_kernel<<<128, 256>>>(t, bih1, bhh1);

        // xi partials: out @ Wif^T  (N=471, K=512 split 2)
        gemm_bt<<<dim3(15, 1, 2), 256>>>(
            p_outb, 512, Wif, 512, p_px, 480, ZX, IFACE, 256, nullptr, nullptr);

        mem_kernel<<<BB, 256, MEM_SMEM_FLOATS * 4>>>(t, bif);
    }

    // final: out[b][t][o] = tanh(ys) @ Wout^T + bout
    tanh_kernel<<<(BB * TT * NNOUT + 255) / 256, 256>>>();
    gemm_bt<<<dim3(256 / 32, (BB * TT) / 64, 1), 256>>>(
        p_ys, NNOUT, Wout, NNOUT, out, 256, 0L, 256, NNOUT, bout, nullptr);
}